// round 16
// baseline (speedup 1.0000x reference)
#include <cuda_runtime.h>

// Problem constants (match reference_code)
#define B_ 16
#define T_ 14
#define F_ 2048
#define NTF (T_ * F_)     // 28672
#define NRE (B_ * NTF)    // 458752

typedef unsigned long long ull;

// ================= packed f32x2 primitives (sm_100+ PTX only) =================
__device__ __forceinline__ ull padd(ull a, ull b) {
    ull r; asm("add.rn.f32x2 %0,%1,%2;" : "=l"(r) : "l"(a), "l"(b)); return r;
}
__device__ __forceinline__ ull psub(ull a, ull b) {
    ull r; asm("sub.rn.f32x2 %0,%1,%2;" : "=l"(r) : "l"(a), "l"(b)); return r;
}
__device__ __forceinline__ ull pmul(ull a, ull b) {
    ull r; asm("mul.rn.f32x2 %0,%1,%2;" : "=l"(r) : "l"(a), "l"(b)); return r;
}
// a*b + c
__device__ __forceinline__ ull pfma(ull a, ull b, ull c) {
    ull r; asm("fma.rn.f32x2 %0,%1,%2,%3;" : "=l"(r) : "l"(a), "l"(b), "l"(c)); return r;
}
__device__ __forceinline__ ull pk(float lo, float hi) {
    ull r;
    asm("mov.b64 %0,{%1,%2};" : "=l"(r) : "r"(__float_as_uint(lo)), "r"(__float_as_uint(hi)));
    return r;
}
__device__ __forceinline__ void upk(ull v, float& lo, float& hi) {
    unsigned ul, uh;
    asm("mov.b64 {%0,%1},%2;" : "=r"(ul), "=r"(uh) : "l"(v));
    lo = __uint_as_float(ul); hi = __uint_as_float(uh);
}
// per-lane rsqrt / reciprocal (MUFU)
__device__ __forceinline__ ull prsqrt(ull v) {
    float lo, hi; upk(v, lo, hi);
    return pk(rsqrtf(lo), rsqrtf(hi));
}
__device__ __forceinline__ ull prcp(ull v) {
    float lo, hi; upk(v, lo, hi);
    return pk(__fdividef(1.0f, lo), __fdividef(1.0f, hi));
}

// streaming 8B load/store (no-reuse data: evict-first policy)
__device__ __forceinline__ ull ldcs8(const float* p) {
    return __ldcs(reinterpret_cast<const ull*>(p));
}
__device__ __forceinline__ void stcs8(float* p, ull v) {
    __stcs(reinterpret_cast<ull*>(p), v);
}

// ================= packed complex (each component is a {f,f+1} pair) =========
struct c2 { ull re, im; };

__device__ __forceinline__ c2 cscale2(c2 a, ull s) { return {pmul(a.re, s), pmul(a.im, s)}; }
__device__ __forceinline__ ull cabs2_2(c2 a) { return pfma(a.im, a.im, pmul(a.re, a.re)); }
// a - b*c
__device__ __forceinline__ c2 csub_mul(c2 a, c2 b, c2 c) {
    ull re = pfma(b.im, c.im, psub(a.re, pmul(b.re, c.re)));
    ull im = psub(psub(a.im, pmul(b.re, c.im)), pmul(b.im, c.re));
    return {re, im};
}
// a - b*conj(c)
__device__ __forceinline__ c2 csub_mulc(c2 a, c2 b, c2 c) {
    ull re = psub(a.re, pfma(b.re, c.re, pmul(b.im, c.im)));
    ull im = pfma(b.re, c.im, psub(a.im, pmul(b.im, c.re)));
    return {re, im};
}

// ================= main kernel: one thread per PAIR of REs ====================
// Champion configuration (fast mode 14.78-14.85us over 6 identical-binary
// draws; occasional slow DVFS draws to 17.4us): 2 REs/thread via packed f32x2,
// nested reverse-Cholesky (one factorization serves all 4 SIC steps), 256
// threads, 2 CTAs/SM. Memory-roofline-bound: 95.6MB obligatory traffic at
// ~6.5 TB/s effective; all instruction/occupancy/pipeline/cache-policy levers
// tested R4-R11 and falsified.
__global__ void __launch_bounds__(256, 2)
sic_lmmse_kernel(const float* __restrict__ yre, const float* __restrict__ yim,
                 const float* __restrict__ hre, const float* __restrict__ him,
                 const int* __restrict__ mask, const float* __restrict__ nv,
                 float* __restrict__ out) {
    const int NP = NTF / 2;  // RE pairs per batch element
    int tid = blockIdx.x * blockDim.x + threadIdx.x;  // exact grid: NRE/2 threads
    int b = tid / NP;
    int tf = (tid - b * NP) * 2;  // even -> 8B-aligned float2 accesses

    float no = nv[0];
    ull no2 = pk(no, no);
    const ull ZERO = 0ULL;                  // {0.f, 0.f}
    const ull ONE2 = 0x3F8000003F800000ULL; // {1.f, 1.f}

    // mask pair -> packed float
    int2 mi = *reinterpret_cast<const int2*>(mask + tf);
    ull m2 = pk((float)mi.x, (float)mi.y);

    int ybase = b * 4 * NTF + tf;
    int hbase = b * 16 * NTF + tf;

    // ---- Gram accumulators (upper tri + real diag) and matched filter z ----
    ull Gd0 = 0, Gd1 = 0, Gd2 = 0, Gd3 = 0;
    c2 G01 = {0, 0}, G02 = {0, 0}, G03 = {0, 0}, G12 = {0, 0}, G13 = {0, 0}, G23 = {0, 0};
    c2 z0 = {0, 0}, z1 = {0, 0}, z2 = {0, 0}, z3 = {0, 0};

#pragma unroll
    for (int r = 0; r < 4; r++) {
        ull Yr = ldcs8(yre + ybase + r * NTF);
        ull Yi = ldcs8(yim + ybase + r * NTF);
        ull hr[4], hi[4], ni[4];
#pragma unroll
        for (int s = 0; s < 4; s++) {
            hr[s] = ldcs8(hre + hbase + (r * 4 + s) * NTF);
            hi[s] = ldcs8(him + hbase + (r * 4 + s) * NTF);
        }
#pragma unroll
        for (int s = 0; s < 4; s++) ni[s] = psub(ZERO, hi[s]);  // -im, keeps FMAs pure

        // diagonals: Gd[s] += |h_s|^2
        Gd0 = pfma(hr[0], hr[0], pfma(hi[0], hi[0], Gd0));
        Gd1 = pfma(hr[1], hr[1], pfma(hi[1], hi[1], Gd1));
        Gd2 = pfma(hr[2], hr[2], pfma(hi[2], hi[2], Gd2));
        Gd3 = pfma(hr[3], hr[3], pfma(hi[3], hi[3], Gd3));

        // off-diagonals: G[s][u] += conj(h_s) * h_u
#define CMAC(ACC, S, U)                                                      \
        ACC.re = pfma(hr[S], hr[U], pfma(hi[S], hi[U], ACC.re));             \
        ACC.im = pfma(hr[S], hi[U], pfma(ni[S], hr[U], ACC.im));
        CMAC(G01, 0, 1) CMAC(G02, 0, 2) CMAC(G03, 0, 3)
        CMAC(G12, 1, 2) CMAC(G13, 1, 3) CMAC(G23, 2, 3)
#undef CMAC

        // z[s] += conj(h_s) * y
#define ZMAC(ACC, S)                                                         \
        ACC.re = pfma(hr[S], Yr, pfma(hi[S], Yi, ACC.re));                   \
        ACC.im = pfma(hr[S], Yi, pfma(ni[S], Yr, ACC.im));
        ZMAC(z0, 0) ZMAC(z1, 1) ZMAC(z2, 2) ZMAC(z3, 3)
#undef ZMAC
    }

    // ---- reverse Cholesky: A = G + no*I = U U^H (U upper). Nested property:
    // A[k:,k:] = U[k:,k:] U[k:,k:]^H for all k, so ONE factorization serves all
    // four SIC steps, and (A_k^{-1})_00 = dinv[k]^2.
    ull dinv3 = prsqrt(padd(Gd3, no2));
    c2 U23 = cscale2(G23, dinv3);
    c2 U13 = cscale2(G13, dinv3);
    c2 U03 = cscale2(G03, dinv3);

    ull dinv2 = prsqrt(psub(padd(Gd2, no2), cabs2_2(U23)));
    c2 U12 = cscale2(csub_mulc(G12, U13, U23), dinv2);
    c2 U02 = cscale2(csub_mulc(G02, U03, U23), dinv2);

    ull dinv1 = prsqrt(psub(psub(padd(Gd1, no2), cabs2_2(U12)), cabs2_2(U13)));
    c2 U01 = cscale2(csub_mulc(csub_mulc(G01, U02, U12), U03, U13), dinv1);

    ull dinv0 = prsqrt(psub(psub(psub(padd(Gd0, no2), cabs2_2(U01)), cabs2_2(U02)), cabs2_2(U03)));

    // ---- one backward solve: w = U^{-1} z ----
    c2 w3 = cscale2(z3, dinv3);
    c2 w2 = cscale2(csub_mul(z2, U23, w3), dinv2);
    c2 w1 = cscale2(csub_mul(csub_mul(z1, U12, w2), U13, w3), dinv1);
    c2 w0 = cscale2(csub_mul(csub_mul(csub_mul(z0, U01, w1), U02, w2), U03, w3), dinv0);

    // ---- 4 SIC steps, each O(1): bias correction + rank-1 w update ----
    c2 x0, x1, x2, x3;
    ull ne0, ne1, ne2, ne3;

    {   // k = 0
        ull noa = pmul(no2, pmul(dinv0, dinv0));
        ull idk = prcp(psub(ONE2, noa));
        c2 xk = cscale2(w0, pmul(dinv0, idk));
        ne0 = pmul(noa, idk);
        x0 = xk;
        w1 = csub_mulc(w1, xk, U01);
        w2 = csub_mulc(w2, xk, U02);
        w3 = csub_mulc(w3, xk, U03);
    }
    {   // k = 1
        ull noa = pmul(no2, pmul(dinv1, dinv1));
        ull idk = prcp(psub(ONE2, noa));
        c2 xk = cscale2(w1, pmul(dinv1, idk));
        ne1 = pmul(noa, idk);
        x1 = xk;
        w2 = csub_mulc(w2, xk, U12);
        w3 = csub_mulc(w3, xk, U13);
    }
    {   // k = 2
        ull noa = pmul(no2, pmul(dinv2, dinv2));
        ull idk = prcp(psub(ONE2, noa));
        c2 xk = cscale2(w2, pmul(dinv2, idk));
        ne2 = pmul(noa, idk);
        x2 = xk;
        w3 = csub_mulc(w3, xk, U23);
    }
    {   // k = 3
        ull noa = pmul(no2, pmul(dinv3, dinv3));
        ull idk = prcp(psub(ONE2, noa));
        x3 = cscale2(w3, pmul(dinv3, idk));
        ne3 = pmul(noa, idk);
    }

    // ---- output: x_ri [2,B,S,T,F] then no_eff [B,S,T,F]; packed 8B stores ----
    const int X = B_ * 4 * NTF;  // 1,835,008
    c2 xs[4] = {x0, x1, x2, x3};
    ull nes[4] = {ne0, ne1, ne2, ne3};
#pragma unroll
    for (int s = 0; s < 4; s++) {
        int base = (b * 4 + s) * NTF + tf;
        stcs8(out + base,         pmul(xs[s].re, m2));
        stcs8(out + X + base,     pmul(xs[s].im, m2));
        stcs8(out + 2 * X + base, pmul(nes[s], m2));
    }
}

extern "C" void kernel_launch(void* const* d_in, const int* in_sizes, int n_in,
                              void* d_out, int out_size) {
    const float* y_re = (const float*)d_in[0];
    const float* y_im = (const float*)d_in[1];
    const float* h_re = (const float*)d_in[2];
    const float* h_im = (const float*)d_in[3];
    const int* mask = (const int*)d_in[4];
    const float* noise_var = (const float*)d_in[5];
    float* out = (float*)d_out;

    const int threads = 256;
    const int blocks = (NRE / 2) / threads;  // exact: 229376 / 256 = 896
    sic_lmmse_kernel<<<blocks, threads>>>(y_re, y_im, h_re, h_im, mask, noise_var, out);
}

// round 17
// speedup vs baseline: 1.0065x; 1.0065x over previous
#include <cuda_runtime.h>

// Problem constants (match reference_code)
#define B_ 16
#define T_ 14
#define F_ 2048
#define NTF (T_ * F_)     // 28672
#define NRE (B_ * NTF)    // 458752

typedef unsigned long long ull;

// ================= packed f32x2 primitives (sm_100+ PTX only) =================
__device__ __forceinline__ ull padd(ull a, ull b) {
    ull r; asm("add.rn.f32x2 %0,%1,%2;" : "=l"(r) : "l"(a), "l"(b)); return r;
}
__device__ __forceinline__ ull psub(ull a, ull b) {
    ull r; asm("sub.rn.f32x2 %0,%1,%2;" : "=l"(r) : "l"(a), "l"(b)); return r;
}
__device__ __forceinline__ ull pmul(ull a, ull b) {
    ull r; asm("mul.rn.f32x2 %0,%1,%2;" : "=l"(r) : "l"(a), "l"(b)); return r;
}
// a*b + c
__device__ __forceinline__ ull pfma(ull a, ull b, ull c) {
    ull r; asm("fma.rn.f32x2 %0,%1,%2,%3;" : "=l"(r) : "l"(a), "l"(b), "l"(c)); return r;
}
__device__ __forceinline__ ull pk(float lo, float hi) {
    ull r;
    asm("mov.b64 %0,{%1,%2};" : "=l"(r) : "r"(__float_as_uint(lo)), "r"(__float_as_uint(hi)));
    return r;
}
__device__ __forceinline__ void upk(ull v, float& lo, float& hi) {
    unsigned ul, uh;
    asm("mov.b64 {%0,%1},%2;" : "=r"(ul), "=r"(uh) : "l"(v));
    lo = __uint_as_float(ul); hi = __uint_as_float(uh);
}
// per-lane rsqrt / reciprocal (MUFU)
__device__ __forceinline__ ull prsqrt(ull v) {
    float lo, hi; upk(v, lo, hi);
    return pk(rsqrtf(lo), rsqrtf(hi));
}
__device__ __forceinline__ ull prcp(ull v) {
    float lo, hi; upk(v, lo, hi);
    return pk(__fdividef(1.0f, lo), __fdividef(1.0f, hi));
}

// streaming 8B load/store (no-reuse data: evict-first policy)
__device__ __forceinline__ ull ldcs8(const float* p) {
    return __ldcs(reinterpret_cast<const ull*>(p));
}
__device__ __forceinline__ void stcs8(float* p, ull v) {
    __stcs(reinterpret_cast<ull*>(p), v);
}

// ================= packed complex (each component is a {f,f+1} pair) =========
struct c2 { ull re, im; };

__device__ __forceinline__ c2 cscale2(c2 a, ull s) { return {pmul(a.re, s), pmul(a.im, s)}; }
__device__ __forceinline__ ull cabs2_2(c2 a) { return pfma(a.im, a.im, pmul(a.re, a.re)); }
// a - b*c
__device__ __forceinline__ c2 csub_mul(c2 a, c2 b, c2 c) {
    ull re = pfma(b.im, c.im, psub(a.re, pmul(b.re, c.re)));
    ull im = psub(psub(a.im, pmul(b.re, c.im)), pmul(b.im, c.re));
    return {re, im};
}
// a - b*conj(c)
__device__ __forceinline__ c2 csub_mulc(c2 a, c2 b, c2 c) {
    ull re = psub(a.re, pfma(b.re, c.re, pmul(b.im, c.im)));
    ull im = pfma(b.re, c.im, psub(a.im, pmul(b.im, c.re)));
    return {re, im};
}

// ================= main kernel: one thread per PAIR of REs ====================
// Champion configuration (fast mode 14.78-14.85us over 7 identical-binary
// draws; occasional slow DVFS draws to 17.4us): 2 REs/thread via packed f32x2,
// nested reverse-Cholesky (one factorization serves all 4 SIC steps), 256
// threads, 2 CTAs/SM. Memory-roofline-bound: 95.6MB obligatory traffic at
// ~6.5 TB/s effective; all instruction/occupancy/pipeline/cache-policy levers
// tested R4-R11 and falsified.
__global__ void __launch_bounds__(256, 2)
sic_lmmse_kernel(const float* __restrict__ yre, const float* __restrict__ yim,
                 const float* __restrict__ hre, const float* __restrict__ him,
                 const int* __restrict__ mask, const float* __restrict__ nv,
                 float* __restrict__ out) {
    const int NP = NTF / 2;  // RE pairs per batch element
    int tid = blockIdx.x * blockDim.x + threadIdx.x;  // exact grid: NRE/2 threads
    int b = tid / NP;
    int tf = (tid - b * NP) * 2;  // even -> 8B-aligned float2 accesses

    float no = nv[0];
    ull no2 = pk(no, no);
    const ull ZERO = 0ULL;                  // {0.f, 0.f}
    const ull ONE2 = 0x3F8000003F800000ULL; // {1.f, 1.f}

    // mask pair -> packed float
    int2 mi = *reinterpret_cast<const int2*>(mask + tf);
    ull m2 = pk((float)mi.x, (float)mi.y);

    int ybase = b * 4 * NTF + tf;
    int hbase = b * 16 * NTF + tf;

    // ---- Gram accumulators (upper tri + real diag) and matched filter z ----
    ull Gd0 = 0, Gd1 = 0, Gd2 = 0, Gd3 = 0;
    c2 G01 = {0, 0}, G02 = {0, 0}, G03 = {0, 0}, G12 = {0, 0}, G13 = {0, 0}, G23 = {0, 0};
    c2 z0 = {0, 0}, z1 = {0, 0}, z2 = {0, 0}, z3 = {0, 0};

#pragma unroll
    for (int r = 0; r < 4; r++) {
        ull Yr = ldcs8(yre + ybase + r * NTF);
        ull Yi = ldcs8(yim + ybase + r * NTF);
        ull hr[4], hi[4], ni[4];
#pragma unroll
        for (int s = 0; s < 4; s++) {
            hr[s] = ldcs8(hre + hbase + (r * 4 + s) * NTF);
            hi[s] = ldcs8(him + hbase + (r * 4 + s) * NTF);
        }
#pragma unroll
        for (int s = 0; s < 4; s++) ni[s] = psub(ZERO, hi[s]);  // -im, keeps FMAs pure

        // diagonals: Gd[s] += |h_s|^2
        Gd0 = pfma(hr[0], hr[0], pfma(hi[0], hi[0], Gd0));
        Gd1 = pfma(hr[1], hr[1], pfma(hi[1], hi[1], Gd1));
        Gd2 = pfma(hr[2], hr[2], pfma(hi[2], hi[2], Gd2));
        Gd3 = pfma(hr[3], hr[3], pfma(hi[3], hi[3], Gd3));

        // off-diagonals: G[s][u] += conj(h_s) * h_u
#define CMAC(ACC, S, U)                                                      \
        ACC.re = pfma(hr[S], hr[U], pfma(hi[S], hi[U], ACC.re));             \
        ACC.im = pfma(hr[S], hi[U], pfma(ni[S], hr[U], ACC.im));
        CMAC(G01, 0, 1) CMAC(G02, 0, 2) CMAC(G03, 0, 3)
        CMAC(G12, 1, 2) CMAC(G13, 1, 3) CMAC(G23, 2, 3)
#undef CMAC

        // z[s] += conj(h_s) * y
#define ZMAC(ACC, S)                                                         \
        ACC.re = pfma(hr[S], Yr, pfma(hi[S], Yi, ACC.re));                   \
        ACC.im = pfma(hr[S], Yi, pfma(ni[S], Yr, ACC.im));
        ZMAC(z0, 0) ZMAC(z1, 1) ZMAC(z2, 2) ZMAC(z3, 3)
#undef ZMAC
    }

    // ---- reverse Cholesky: A = G + no*I = U U^H (U upper). Nested property:
    // A[k:,k:] = U[k:,k:] U[k:,k:]^H for all k, so ONE factorization serves all
    // four SIC steps, and (A_k^{-1})_00 = dinv[k]^2.
    ull dinv3 = prsqrt(padd(Gd3, no2));
    c2 U23 = cscale2(G23, dinv3);
    c2 U13 = cscale2(G13, dinv3);
    c2 U03 = cscale2(G03, dinv3);

    ull dinv2 = prsqrt(psub(padd(Gd2, no2), cabs2_2(U23)));
    c2 U12 = cscale2(csub_mulc(G12, U13, U23), dinv2);
    c2 U02 = cscale2(csub_mulc(G02, U03, U23), dinv2);

    ull dinv1 = prsqrt(psub(psub(padd(Gd1, no2), cabs2_2(U12)), cabs2_2(U13)));
    c2 U01 = cscale2(csub_mulc(csub_mulc(G01, U02, U12), U03, U13), dinv1);

    ull dinv0 = prsqrt(psub(psub(psub(padd(Gd0, no2), cabs2_2(U01)), cabs2_2(U02)), cabs2_2(U03)));

    // ---- one backward solve: w = U^{-1} z ----
    c2 w3 = cscale2(z3, dinv3);
    c2 w2 = cscale2(csub_mul(z2, U23, w3), dinv2);
    c2 w1 = cscale2(csub_mul(csub_mul(z1, U12, w2), U13, w3), dinv1);
    c2 w0 = cscale2(csub_mul(csub_mul(csub_mul(z0, U01, w1), U02, w2), U03, w3), dinv0);

    // ---- 4 SIC steps, each O(1): bias correction + rank-1 w update ----
    c2 x0, x1, x2, x3;
    ull ne0, ne1, ne2, ne3;

    {   // k = 0
        ull noa = pmul(no2, pmul(dinv0, dinv0));
        ull idk = prcp(psub(ONE2, noa));
        c2 xk = cscale2(w0, pmul(dinv0, idk));
        ne0 = pmul(noa, idk);
        x0 = xk;
        w1 = csub_mulc(w1, xk, U01);
        w2 = csub_mulc(w2, xk, U02);
        w3 = csub_mulc(w3, xk, U03);
    }
    {   // k = 1
        ull noa = pmul(no2, pmul(dinv1, dinv1));
        ull idk = prcp(psub(ONE2, noa));
        c2 xk = cscale2(w1, pmul(dinv1, idk));
        ne1 = pmul(noa, idk);
        x1 = xk;
        w2 = csub_mulc(w2, xk, U12);
        w3 = csub_mulc(w3, xk, U13);
    }
    {   // k = 2
        ull noa = pmul(no2, pmul(dinv2, dinv2));
        ull idk = prcp(psub(ONE2, noa));
        c2 xk = cscale2(w2, pmul(dinv2, idk));
        ne2 = pmul(noa, idk);
        x2 = xk;
        w3 = csub_mulc(w3, xk, U23);
    }
    {   // k = 3
        ull noa = pmul(no2, pmul(dinv3, dinv3));
        ull idk = prcp(psub(ONE2, noa));
        x3 = cscale2(w3, pmul(dinv3, idk));
        ne3 = pmul(noa, idk);
    }

    // ---- output: x_ri [2,B,S,T,F] then no_eff [B,S,T,F]; packed 8B stores ----
    const int X = B_ * 4 * NTF;  // 1,835,008
    c2 xs[4] = {x0, x1, x2, x3};
    ull nes[4] = {ne0, ne1, ne2, ne3};
#pragma unroll
    for (int s = 0; s < 4; s++) {
        int base = (b * 4 + s) * NTF + tf;
        stcs8(out + base,         pmul(xs[s].re, m2));
        stcs8(out + X + base,     pmul(xs[s].im, m2));
        stcs8(out + 2 * X + base, pmul(nes[s], m2));
    }
}

extern "C" void kernel_launch(void* const* d_in, const int* in_sizes, int n_in,
                              void* d_out, int out_size) {
    const float* y_re = (const float*)d_in[0];
    const float* y_im = (const float*)d_in[1];
    const float* h_re = (const float*)d_in[2];
    const float* h_im = (const float*)d_in[3];
    const int* mask = (const int*)d_in[4];
    const float* noise_var = (const float*)d_in[5];
    float* out = (float*)d_out;

    const int threads = 256;
    const int blocks = (NRE / 2) / threads;  // exact: 229376 / 256 = 896
    sic_lmmse_kernel<<<blocks, threads>>>(y_re, y_im, h_re, h_im, mask, noise_var, out);
}